// round 1
// baseline (speedup 1.0000x reference)
#include <cuda_runtime.h>

#define HH 128
#define WW 128
#define CC 64
#define NPIX (HH*WW)
#define GSTR 129

// scratch (allocation-free: __device__ globals)
__device__ float g_q[HH*CC*WW];   // [h][c][w]
__device__ float g_k[HH*CC*WW];   // [h][c][w]
__device__ float g_v[CC*HH*WW];   // [c][h][w]
__device__ float g_S[HH*WW*WW];   // [r][w][k]
__device__ float g_tmp[CC*HH*WW]; // [c][h][k] horizontal 7-sum of v
__device__ float g_vs[HH*CC*WW];  // [h][c][k] full 7x7 box sum of v

// ---------------------------------------------------------------------------
// QKV: out[o,n] = sum_c W[o,c]*x[c,n] + b[o].  dest: 0=q,1=k (layout [h][c][w]),
// 2=v (layout [c][h][w]).
// ---------------------------------------------------------------------------
__global__ __launch_bounds__(256) void qkv_kernel(const float* __restrict__ x,
                                                  const float* __restrict__ Wm,
                                                  const float* __restrict__ bias,
                                                  int dest)
{
    __shared__ float Ws[64*64];
    __shared__ float bs[64];
    int tid = threadIdx.x;
    for (int i = tid; i < 4096; i += 256) Ws[i] = Wm[i];
    if (tid < 64) bs[tid] = bias[tid];
    __syncthreads();

    int n = blockIdx.x * 64 + (tid & 63);
    int quarter = tid >> 6;
    float acc[16];
    #pragma unroll
    for (int i = 0; i < 16; i++) acc[i] = 0.f;

    #pragma unroll 4
    for (int c = 0; c < 64; c++) {
        float xv = x[c * NPIX + n];
        #pragma unroll
        for (int i = 0; i < 16; i++)
            acc[i] += Ws[(quarter*16 + i)*64 + c] * xv;
    }

    float* out = (dest == 0) ? g_q : (dest == 1) ? g_k : g_v;
    int h = n >> 7, w = n & 127;
    if (dest < 2) {
        #pragma unroll
        for (int i = 0; i < 16; i++)
            out[h*(CC*WW) + (quarter*16 + i)*WW + w] = acc[i] + bs[quarter*16 + i];
    } else {
        #pragma unroll
        for (int i = 0; i < 16; i++)
            out[(quarter*16 + i)*NPIX + n] = acc[i] + bs[quarter*16 + i];
    }
}

// ---------------------------------------------------------------------------
// Per-row Gram G_r = Q_r^T K_r (64-deep), then diagonal 7-sum -> S_r.
// One block per row r. Dyn smem: Qs(8192) + Ks(8192) + G(128*129) floats.
// ---------------------------------------------------------------------------
__global__ __launch_bounds__(256) void rowgram_kernel()
{
    extern __shared__ float sm[];
    float* Qs = sm;            // 64 x 128
    float* Ks = sm + 8192;     // 64 x 128
    float* G  = sm + 16384;    // 128 x GSTR

    int r = blockIdx.x;
    int tid = threadIdx.x;
    const float* qrow = g_q + r * 8192;
    const float* krow = g_k + r * 8192;
    for (int i = tid; i < 8192; i += 256) { Qs[i] = qrow[i]; Ks[i] = krow[i]; }
    __syncthreads();

    int lane = tid & 31, warp = tid >> 5;
    int b0 = warp * 16;
    float acc[4][16];
    #pragma unroll
    for (int m = 0; m < 4; m++)
        #pragma unroll
        for (int j = 0; j < 16; j++) acc[m][j] = 0.f;

    for (int c = 0; c < 64; c++) {
        float qv[4];
        #pragma unroll
        for (int m = 0; m < 4; m++) qv[m] = Qs[c*128 + lane + 32*m];
        #pragma unroll
        for (int j = 0; j < 16; j++) {
            float kv = Ks[c*128 + b0 + j];
            #pragma unroll
            for (int m = 0; m < 4; m++) acc[m][j] += qv[m] * kv;
        }
    }
    #pragma unroll
    for (int m = 0; m < 4; m++)
        #pragma unroll
        for (int j = 0; j < 16; j++)
            G[(lane + 32*m)*GSTR + b0 + j] = acc[m][j];
    __syncthreads();

    // S_r[w,k] = sum_{j=0..6} G[w-3+j, k-3+j] (OOB terms are zero)
    float* Sout = g_S + r * 16384;
    for (int idx = tid; idx < 16384; idx += 256) {
        int w = idx >> 7, k = idx & 127;
        float s = 0.f;
        #pragma unroll
        for (int j = 0; j < 7; j++) {
            int a = w - 3 + j, b = k - 3 + j;
            if (a >= 0 && a < 128 && b >= 0 && b < 128)
                s += G[a*GSTR + b];
        }
        Sout[idx] = s;
    }
}

// ---------------------------------------------------------------------------
// Separable 7x7 box sum of v. Pass 1: horizontal (k), pass 2: vertical (h),
// writing vs in [h][c][k] layout.
// ---------------------------------------------------------------------------
__global__ __launch_bounds__(256) void hbox_kernel()
{
    int idx = blockIdx.x * 256 + threadIdx.x;   // over [c][h][k]
    int k = idx & 127;
    float s = 0.f;
    #pragma unroll
    for (int j = 0; j < 7; j++) {
        int kk = k - 3 + j;
        if (kk >= 0 && kk < 128) s += g_v[idx + (kk - k)];
    }
    g_tmp[idx] = s;
}

__global__ __launch_bounds__(256) void vbox_kernel()
{
    int idx = blockIdx.x * 256 + threadIdx.x;   // over [h][c][k]
    int h = idx >> 13;
    int c = (idx >> 7) & 63;
    int k = idx & 127;
    float s = 0.f;
    #pragma unroll
    for (int i = 0; i < 7; i++) {
        int hh = h - 3 + i;
        if (hh >= 0 && hh < 128) s += g_tmp[c*NPIX + hh*128 + k];
    }
    g_vs[idx] = s;
}

// ---------------------------------------------------------------------------
// Per output row h: attn = softmax_k(sum_{i} S_{h-3+i}), out = attn @ vs_h^T.
// Dyn smem: A(128*GSTR) + Vs(8192) floats.
// ---------------------------------------------------------------------------
__global__ __launch_bounds__(256) void attn_out_kernel(float* __restrict__ out)
{
    extern __shared__ float sm[];
    float* A  = sm;                 // [w][k], stride GSTR
    float* Vs = sm + 128*GSTR;      // [c][k]

    int h = blockIdx.x;
    int tid = threadIdx.x;
    int lane = tid & 31, warp = tid >> 5;

    int r0 = (h - 3 < 0) ? 0 : h - 3;
    int r1 = (h + 3 > 127) ? 127 : h + 3;
    for (int idx = tid; idx < 16384; idx += 256) {
        float s = 0.f;
        for (int r = r0; r <= r1; r++) s += g_S[r*16384 + idx];
        int w = idx >> 7, k = idx & 127;
        A[w*GSTR + k] = s;
    }
    const float* vrow = g_vs + h * 8192;
    for (int i = tid; i < 8192; i += 256) Vs[i] = vrow[i];
    __syncthreads();

    // softmax over k: one warp per w-row
    for (int w = warp; w < 128; w += 8) {
        float v[4];
        #pragma unroll
        for (int m = 0; m < 4; m++) v[m] = A[w*GSTR + lane + 32*m];
        float mx = fmaxf(fmaxf(v[0], v[1]), fmaxf(v[2], v[3]));
        #pragma unroll
        for (int off = 16; off > 0; off >>= 1)
            mx = fmaxf(mx, __shfl_xor_sync(0xffffffffu, mx, off));
        float e[4], s = 0.f;
        #pragma unroll
        for (int m = 0; m < 4; m++) { e[m] = __expf(v[m] - mx); s += e[m]; }
        #pragma unroll
        for (int off = 16; off > 0; off >>= 1)
            s += __shfl_xor_sync(0xffffffffu, s, off);
        float inv = 1.f / s;
        #pragma unroll
        for (int m = 0; m < 4; m++) A[w*GSTR + lane + 32*m] = e[m] * inv;
    }
    __syncthreads();

    // out[c,h,w] = sum_k A[w][k] * Vs[c][k]
    int c0 = warp * 8;
    float acc[8][4];
    #pragma unroll
    for (int i = 0; i < 8; i++)
        #pragma unroll
        for (int m = 0; m < 4; m++) acc[i][m] = 0.f;

    for (int k = 0; k < 128; k++) {
        float a[4];
        #pragma unroll
        for (int m = 0; m < 4; m++) a[m] = A[(lane + 32*m)*GSTR + k];
        #pragma unroll
        for (int i = 0; i < 8; i++) {
            float vv = Vs[(c0 + i)*128 + k];
            #pragma unroll
            for (int m = 0; m < 4; m++) acc[i][m] += vv * a[m];
        }
    }
    #pragma unroll
    for (int i = 0; i < 8; i++)
        #pragma unroll
        for (int m = 0; m < 4; m++)
            out[(c0 + i)*NPIX + h*128 + lane + 32*m] = acc[i][m];
}

// ---------------------------------------------------------------------------
extern "C" void kernel_launch(void* const* d_in, const int* in_sizes, int n_in,
                              void* d_out, int out_size)
{
    const float* x  = (const float*)d_in[0];
    const float* Wq = (const float*)d_in[1];
    const float* bq = (const float*)d_in[2];
    const float* Wk = (const float*)d_in[3];
    const float* bk = (const float*)d_in[4];
    const float* Wv = (const float*)d_in[5];
    const float* bv = (const float*)d_in[6];
    float* out = (float*)d_out;

    const int smem2 = (8192 + 8192 + 128*GSTR) * 4;   // 131584 B
    const int smem4 = (128*GSTR + 8192) * 4;          //  98816 B
    cudaFuncSetAttribute(rowgram_kernel,  cudaFuncAttributeMaxDynamicSharedMemorySize, smem2);
    cudaFuncSetAttribute(attn_out_kernel, cudaFuncAttributeMaxDynamicSharedMemorySize, smem4);

    qkv_kernel<<<256, 256>>>(x, Wq, bq, 0);
    qkv_kernel<<<256, 256>>>(x, Wk, bk, 1);
    qkv_kernel<<<256, 256>>>(x, Wv, bv, 2);
    rowgram_kernel<<<128, 256, smem2>>>();
    hbox_kernel<<<4096, 256>>>();
    vbox_kernel<<<4096, 256>>>();
    attn_out_kernel<<<128, 256, smem4>>>(out);
}

// round 2
// speedup vs baseline: 1.3318x; 1.3318x over previous
#include <cuda_runtime.h>

#define HH 128
#define WW 128
#define CC 64
#define NPIX (HH*WW)
#define GSTR 129

// scratch (allocation-free: __device__ globals)
__device__ float g_q[HH*CC*WW];   // [h][c][w]
__device__ float g_k[HH*CC*WW];   // [h][c][w]
__device__ float g_v[CC*HH*WW];   // [c][h][w]
__device__ float g_S[HH*WW*WW];   // [r][w][k]
__device__ float g_tmp[CC*HH*WW]; // [c][h][k] horizontal 7-sum of v
__device__ float g_vs[HH*CC*WW];  // [h][c][k] full 7x7 box sum of v

// ---------------------------------------------------------------------------
// Fused QKV: grid (32, 3); blockIdx.y selects which of q/k/v this block does.
// 512 threads; each thread: 4 pixels x 16 out-channels register tile.
// q,k layout [h][c][w]; v layout [c][h][w].
// ---------------------------------------------------------------------------
__global__ __launch_bounds__(512) void qkv_kernel(const float* __restrict__ x,
                                                  const float* __restrict__ Wq,
                                                  const float* __restrict__ bq,
                                                  const float* __restrict__ Wk,
                                                  const float* __restrict__ bk,
                                                  const float* __restrict__ Wv,
                                                  const float* __restrict__ bv)
{
    __shared__ float Ws[64*64];
    __shared__ float bs[64];
    int dest = blockIdx.y;
    const float* Wm   = (dest == 0) ? Wq : (dest == 1) ? Wk : Wv;
    const float* bias = (dest == 0) ? bq : (dest == 1) ? bk : bv;
    int tid = threadIdx.x;
    for (int i = tid; i < 4096; i += 512) Ws[i] = Wm[i];
    if (tid < 64) bs[tid] = bias[tid];
    __syncthreads();

    int slot = tid & 127;            // pixel slot within block
    int quarter = tid >> 7;          // channel quarter (16 ch each)
    int nbase = blockIdx.x * 512 + slot;

    float acc[16][4];
    #pragma unroll
    for (int i = 0; i < 16; i++)
        #pragma unroll
        for (int p = 0; p < 4; p++) acc[i][p] = 0.f;

    #pragma unroll 2
    for (int c = 0; c < 64; c++) {
        float xv[4];
        #pragma unroll
        for (int p = 0; p < 4; p++) xv[p] = x[c * NPIX + nbase + 128 * p];
        #pragma unroll
        for (int i = 0; i < 16; i++) {
            float wv = Ws[(quarter*16 + i)*64 + c];
            #pragma unroll
            for (int p = 0; p < 4; p++) acc[i][p] += wv * xv[p];
        }
    }

    float* out = (dest == 0) ? g_q : (dest == 1) ? g_k : g_v;
    #pragma unroll
    for (int i = 0; i < 16; i++) {
        int ch = quarter*16 + i;
        float b = bs[ch];
        #pragma unroll
        for (int p = 0; p < 4; p++) {
            int n = nbase + 128 * p;
            float val = acc[i][p] + b;
            if (dest < 2) {
                int h = n >> 7, w = n & 127;
                out[h*(CC*WW) + ch*WW + w] = val;
            } else {
                out[ch*NPIX + n] = val;
            }
        }
    }
}

// ---------------------------------------------------------------------------
// Per-row Gram G_r = Q_r^T K_r (64-deep), then diagonal 7-sum -> S_r.
// One block (512 threads) per row r.
// ---------------------------------------------------------------------------
__global__ __launch_bounds__(512) void rowgram_kernel()
{
    extern __shared__ float sm[];
    float* Qs = sm;            // 64 x 128
    float* Ks = sm + 8192;     // 64 x 128
    float* G  = sm + 16384;    // 128 x GSTR

    int r = blockIdx.x;
    int tid = threadIdx.x;
    const float* qrow = g_q + r * 8192;
    const float* krow = g_k + r * 8192;
    for (int i = tid; i < 8192; i += 512) { Qs[i] = qrow[i]; Ks[i] = krow[i]; }
    __syncthreads();

    int lane = tid & 31, warp = tid >> 5;    // 16 warps
    int b0 = warp * 8;
    float acc[4][8];
    #pragma unroll
    for (int m = 0; m < 4; m++)
        #pragma unroll
        for (int j = 0; j < 8; j++) acc[m][j] = 0.f;

    #pragma unroll 4
    for (int c = 0; c < 64; c++) {
        float qv[4];
        #pragma unroll
        for (int m = 0; m < 4; m++) qv[m] = Qs[c*128 + lane + 32*m];
        #pragma unroll
        for (int j = 0; j < 8; j++) {
            float kv = Ks[c*128 + b0 + j];
            #pragma unroll
            for (int m = 0; m < 4; m++) acc[m][j] += qv[m] * kv;
        }
    }
    #pragma unroll
    for (int m = 0; m < 4; m++)
        #pragma unroll
        for (int j = 0; j < 8; j++)
            G[(lane + 32*m)*GSTR + b0 + j] = acc[m][j];
    __syncthreads();

    // S_r[w,k] = sum_{j=0..6} G[w-3+j, k-3+j] (OOB terms are zero)
    float* Sout = g_S + r * 16384;
    for (int idx = tid; idx < 16384; idx += 512) {
        int w = idx >> 7, k = idx & 127;
        float s = 0.f;
        #pragma unroll
        for (int j = 0; j < 7; j++) {
            int a = w - 3 + j, b = k - 3 + j;
            if (a >= 0 && a < 128 && b >= 0 && b < 128)
                s += G[a*GSTR + b];
        }
        Sout[idx] = s;
    }
}

// ---------------------------------------------------------------------------
// Separable 7x7 box sum of v. Pass 1: horizontal (k), pass 2: vertical (h),
// writing vs in [h][c][k] layout.
// ---------------------------------------------------------------------------
__global__ __launch_bounds__(256) void hbox_kernel()
{
    int idx = blockIdx.x * 256 + threadIdx.x;   // over [c][h][k]
    int k = idx & 127;
    float s = 0.f;
    #pragma unroll
    for (int j = 0; j < 7; j++) {
        int kk = k - 3 + j;
        if (kk >= 0 && kk < 128) s += g_v[idx + (kk - k)];
    }
    g_tmp[idx] = s;
}

__global__ __launch_bounds__(256) void vbox_kernel()
{
    int idx = blockIdx.x * 256 + threadIdx.x;   // over [h][c][k]
    int h = idx >> 13;
    int c = (idx >> 7) & 63;
    int k = idx & 127;
    float s = 0.f;
    #pragma unroll
    for (int i = 0; i < 7; i++) {
        int hh = h - 3 + i;
        if (hh >= 0 && hh < 128) s += g_tmp[c*NPIX + hh*128 + k];
    }
    g_vs[idx] = s;
}

// ---------------------------------------------------------------------------
// Per output row h (512 threads): attn = softmax_k(sum_i S_{h-3+i}),
// out = attn @ vs_h^T.
// ---------------------------------------------------------------------------
__global__ __launch_bounds__(512) void attn_out_kernel(float* __restrict__ out)
{
    extern __shared__ float sm[];
    float* A  = sm;                 // [w][k], stride GSTR
    float* Vs = sm + 128*GSTR;      // [c][k]

    int h = blockIdx.x;
    int tid = threadIdx.x;
    int lane = tid & 31, warp = tid >> 5;    // 16 warps

    int r0 = (h - 3 < 0) ? 0 : h - 3;
    int r1 = (h + 3 > 127) ? 127 : h + 3;
    for (int idx = tid; idx < 16384; idx += 512) {
        float s = 0.f;
        for (int r = r0; r <= r1; r++) s += g_S[r*16384 + idx];
        int w = idx >> 7, k = idx & 127;
        A[w*GSTR + k] = s;
    }
    const float* vrow = g_vs + h * 8192;
    for (int i = tid; i < 8192; i += 512) Vs[i] = vrow[i];
    __syncthreads();

    // softmax over k: one warp per w-row, 16 warps cover 128 rows
    for (int w = warp; w < 128; w += 16) {
        float v[4];
        #pragma unroll
        for (int m = 0; m < 4; m++) v[m] = A[w*GSTR + lane + 32*m];
        float mx = fmaxf(fmaxf(v[0], v[1]), fmaxf(v[2], v[3]));
        #pragma unroll
        for (int off = 16; off > 0; off >>= 1)
            mx = fmaxf(mx, __shfl_xor_sync(0xffffffffu, mx, off));
        float e[4], s = 0.f;
        #pragma unroll
        for (int m = 0; m < 4; m++) { e[m] = __expf(v[m] - mx); s += e[m]; }
        #pragma unroll
        for (int off = 16; off > 0; off >>= 1)
            s += __shfl_xor_sync(0xffffffffu, s, off);
        float inv = 1.f / s;
        #pragma unroll
        for (int m = 0; m < 4; m++) A[w*GSTR + lane + 32*m] = e[m] * inv;
    }
    __syncthreads();

    // out[c,h,w] = sum_k A[w][k] * Vs[c][k]; 16 warps x 4 channels each
    int c0 = warp * 4;
    float acc[4][4];
    #pragma unroll
    for (int i = 0; i < 4; i++)
        #pragma unroll
        for (int m = 0; m < 4; m++) acc[i][m] = 0.f;

    #pragma unroll 4
    for (int k = 0; k < 128; k++) {
        float a[4];
        #pragma unroll
        for (int m = 0; m < 4; m++) a[m] = A[(lane + 32*m)*GSTR + k];
        #pragma unroll
        for (int i = 0; i < 4; i++) {
            float vv = Vs[(c0 + i)*128 + k];
            #pragma unroll
            for (int m = 0; m < 4; m++) acc[i][m] += vv * a[m];
        }
    }
    #pragma unroll
    for (int i = 0; i < 4; i++)
        #pragma unroll
        for (int m = 0; m < 4; m++)
            out[(c0 + i)*NPIX + h*128 + lane + 32*m] = acc[i][m];
}

// ---------------------------------------------------------------------------
extern "C" void kernel_launch(void* const* d_in, const int* in_sizes, int n_in,
                              void* d_out, int out_size)
{
    const float* x  = (const float*)d_in[0];
    const float* Wq = (const float*)d_in[1];
    const float* bq = (const float*)d_in[2];
    const float* Wk = (const float*)d_in[3];
    const float* bk = (const float*)d_in[4];
    const float* Wv = (const float*)d_in[5];
    const float* bv = (const float*)d_in[6];
    float* out = (float*)d_out;

    const int smem2 = (8192 + 8192 + 128*GSTR) * 4;   // 131584 B
    const int smem4 = (128*GSTR + 8192) * 4;          //  98816 B
    cudaFuncSetAttribute(rowgram_kernel,  cudaFuncAttributeMaxDynamicSharedMemorySize, smem2);
    cudaFuncSetAttribute(attn_out_kernel, cudaFuncAttributeMaxDynamicSharedMemorySize, smem4);

    dim3 qkv_grid(32, 3);
    qkv_kernel<<<qkv_grid, 512>>>(x, Wq, bq, Wk, bk, Wv, bv);
    rowgram_kernel<<<128, 512, smem2>>>();
    hbox_kernel<<<4096, 256>>>();
    vbox_kernel<<<4096, 256>>>();
    attn_out_kernel<<<128, 512, smem4>>>(out);
}

// round 3
// speedup vs baseline: 1.5464x; 1.1611x over previous
#include <cuda_runtime.h>

#define HH 128
#define WW 128
#define CC 64
#define NPIX (HH*WW)
#define GSTR 129

// scratch (allocation-free: __device__ globals)
__device__ float g_q[HH*CC*WW];   // [h][c][w]
__device__ float g_k[HH*CC*WW];   // [h][c][w]
__device__ float g_v[CC*HH*WW];   // [c][h][w]
__device__ float g_S[HH*WW*WW];   // [r][w][k]  (after prefix: PS over r)
__device__ float g_tmp[CC*HH*WW]; // [c][h][k]  (after prefix: prefix over h)

// ---------------------------------------------------------------------------
// Fused QKV: grid (32, 3); blockIdx.y selects which of q/k/v this block does.
// ---------------------------------------------------------------------------
__global__ __launch_bounds__(512) void qkv_kernel(const float* __restrict__ x,
                                                  const float* __restrict__ Wq,
                                                  const float* __restrict__ bq,
                                                  const float* __restrict__ Wk,
                                                  const float* __restrict__ bk,
                                                  const float* __restrict__ Wv,
                                                  const float* __restrict__ bv)
{
    __shared__ float Ws[64*64];
    __shared__ float bs[64];
    int dest = blockIdx.y;
    const float* Wm   = (dest == 0) ? Wq : (dest == 1) ? Wk : Wv;
    const float* bias = (dest == 0) ? bq : (dest == 1) ? bk : bv;
    int tid = threadIdx.x;
    for (int i = tid; i < 4096; i += 512) Ws[i] = Wm[i];
    if (tid < 64) bs[tid] = bias[tid];
    __syncthreads();

    int slot = tid & 127;
    int quarter = tid >> 7;
    int nbase = blockIdx.x * 512 + slot;

    float acc[16][4];
    #pragma unroll
    for (int i = 0; i < 16; i++)
        #pragma unroll
        for (int p = 0; p < 4; p++) acc[i][p] = 0.f;

    #pragma unroll 2
    for (int c = 0; c < 64; c++) {
        float xv[4];
        #pragma unroll
        for (int p = 0; p < 4; p++) xv[p] = x[c * NPIX + nbase + 128 * p];
        #pragma unroll
        for (int i = 0; i < 16; i++) {
            float wv = Ws[(quarter*16 + i)*64 + c];
            #pragma unroll
            for (int p = 0; p < 4; p++) acc[i][p] += wv * xv[p];
        }
    }

    float* out = (dest == 0) ? g_q : (dest == 1) ? g_k : g_v;
    #pragma unroll
    for (int i = 0; i < 16; i++) {
        int ch = quarter*16 + i;
        float b = bs[ch];
        #pragma unroll
        for (int p = 0; p < 4; p++) {
            int n = nbase + 128 * p;
            float val = acc[i][p] + b;
            if (dest < 2) {
                int h = n >> 7, w = n & 127;
                out[h*(CC*WW) + ch*WW + w] = val;
            } else {
                out[ch*NPIX + n] = val;
            }
        }
    }
}

// ---------------------------------------------------------------------------
// Per-row Gram G_r = Q_r^T K_r (64-deep), then diagonal 7-sum -> S_r.
// ---------------------------------------------------------------------------
__global__ __launch_bounds__(512) void rowgram_kernel()
{
    extern __shared__ float sm[];
    float* Qs = sm;            // 64 x 128
    float* Ks = sm + 8192;     // 64 x 128
    float* G  = sm + 16384;    // 128 x GSTR

    int r = blockIdx.x;
    int tid = threadIdx.x;
    const float* qrow = g_q + r * 8192;
    const float* krow = g_k + r * 8192;
    for (int i = tid; i < 8192; i += 512) { Qs[i] = qrow[i]; Ks[i] = krow[i]; }
    __syncthreads();

    int lane = tid & 31, warp = tid >> 5;    // 16 warps
    int b0 = warp * 8;
    float acc[4][8];
    #pragma unroll
    for (int m = 0; m < 4; m++)
        #pragma unroll
        for (int j = 0; j < 8; j++) acc[m][j] = 0.f;

    #pragma unroll 4
    for (int c = 0; c < 64; c++) {
        float qv[4];
        #pragma unroll
        for (int m = 0; m < 4; m++) qv[m] = Qs[c*128 + lane + 32*m];
        #pragma unroll
        for (int j = 0; j < 8; j++) {
            float kv = Ks[c*128 + b0 + j];
            #pragma unroll
            for (int m = 0; m < 4; m++) acc[m][j] += qv[m] * kv;
        }
    }
    #pragma unroll
    for (int m = 0; m < 4; m++)
        #pragma unroll
        for (int j = 0; j < 8; j++)
            G[(lane + 32*m)*GSTR + b0 + j] = acc[m][j];
    __syncthreads();

    // S_r[w,k] = sum_{j=0..6} G[w-3+j, k-3+j] (OOB terms are zero)
    float* Sout = g_S + r * 16384;
    for (int idx = tid; idx < 16384; idx += 512) {
        int w = idx >> 7, k = idx & 127;
        float s = 0.f;
        #pragma unroll
        for (int j = 0; j < 7; j++) {
            int a = w - 3 + j, b = k - 3 + j;
            if (a >= 0 && a < 128 && b >= 0 && b < 128)
                s += G[a*GSTR + b];
        }
        Sout[idx] = s;
    }
}

// ---------------------------------------------------------------------------
// Horizontal 7-sum of v (over k).
// ---------------------------------------------------------------------------
__global__ __launch_bounds__(256) void hbox_kernel()
{
    int idx = blockIdx.x * 256 + threadIdx.x;   // over [c][h][k]
    int k = idx & 127;
    float s = 0.f;
    #pragma unroll
    for (int j = 0; j < 7; j++) {
        int kk = k - 3 + j;
        if (kk >= 0 && kk < 128) s += g_v[idx + (kk - k)];
    }
    g_tmp[idx] = s;
}

// ---------------------------------------------------------------------------
// In-place prefix sums: g_S over r (16384 chains), g_tmp over h (8192 chains).
// 96 blocks x 256 threads = 24576 threads, one chain each.
// ---------------------------------------------------------------------------
__global__ __launch_bounds__(256) void prefix_kernel()
{
    int t = blockIdx.x * 256 + threadIdx.x;
    if (t < 16384) {
        float s = 0.f;
        float* p = g_S + t;
        #pragma unroll 4
        for (int r = 0; r < 128; r++) {
            s += p[r * 16384];
            p[r * 16384] = s;
        }
    } else {
        int u = t - 16384;           // (c,k) chain: c = u>>7, k = u&127
        int c = u >> 7, k = u & 127;
        float s = 0.f;
        float* p = g_tmp + c * NPIX + k;
        #pragma unroll 4
        for (int h = 0; h < 128; h++) {
            s += p[h * 128];
            p[h * 128] = s;
        }
    }
}

// ---------------------------------------------------------------------------
// Per (h, w-half): A = PS[r1]-PS[r0-1]; softmax_k; Vs = Ptmp diff;
// out = attn @ Vs^T. 256 blocks x 256 threads, ~66KB smem -> 3 blocks/SM.
// ---------------------------------------------------------------------------
__global__ __launch_bounds__(256) void attn_out_kernel(float* __restrict__ out)
{
    extern __shared__ float sm[];
    float* A  = sm;                 // [64 local w][k], stride GSTR
    float* Vs = sm + 64*GSTR;       // [c=64][k=128]

    int h    = blockIdx.x >> 1;
    int half = blockIdx.x & 1;
    int tid = threadIdx.x;
    int lane = tid & 31, warp = tid >> 5;    // 8 warps

    int r0 = (h - 3 < 0) ? 0 : h - 3;
    int r1 = (h + 3 > 127) ? 127 : h + 3;
    const float* PS1 = g_S + r1 * 16384 + half * 8192;
    const float* PS0 = (r0 > 0) ? (g_S + (r0 - 1) * 16384 + half * 8192) : nullptr;
    for (int idx = tid; idx < 8192; idx += 256) {
        float s = PS1[idx];
        if (PS0) s -= PS0[idx];
        int wl = idx >> 7, k = idx & 127;
        A[wl*GSTR + k] = s;
    }

    int top = (h + 3 > 127) ? 127 : h + 3;
    int bot = h - 4;
    for (int i = tid; i < 8192; i += 256) {
        int c = i >> 7, k = i & 127;
        float s = g_tmp[c*NPIX + top*128 + k];
        if (bot >= 0) s -= g_tmp[c*NPIX + bot*128 + k];
        Vs[c*128 + k] = s;
    }
    __syncthreads();

    // softmax over k: one warp per local-w row (8 warps cover 64 rows)
    for (int w = warp; w < 64; w += 8) {
        float v[4];
        #pragma unroll
        for (int m = 0; m < 4; m++) v[m] = A[w*GSTR + lane + 32*m];
        float mx = fmaxf(fmaxf(v[0], v[1]), fmaxf(v[2], v[3]));
        #pragma unroll
        for (int off = 16; off > 0; off >>= 1)
            mx = fmaxf(mx, __shfl_xor_sync(0xffffffffu, mx, off));
        float e[4], s = 0.f;
        #pragma unroll
        for (int m = 0; m < 4; m++) { e[m] = __expf(v[m] - mx); s += e[m]; }
        #pragma unroll
        for (int off = 16; off > 0; off >>= 1)
            s += __shfl_xor_sync(0xffffffffu, s, off);
        float inv = 1.f / s;
        #pragma unroll
        for (int m = 0; m < 4; m++) A[w*GSTR + lane + 32*m] = e[m] * inv;
    }
    __syncthreads();

    // out[c, h, half*64 + w] = sum_k A[w][k] * Vs[c][k]
    // 8 warps x 8 channels each; each thread 8c x 2w.
    int c0 = warp * 8;
    float acc[8][2];
    #pragma unroll
    for (int i = 0; i < 8; i++)
        #pragma unroll
        for (int m = 0; m < 2; m++) acc[i][m] = 0.f;

    #pragma unroll 4
    for (int k = 0; k < 128; k++) {
        float a[2];
        #pragma unroll
        for (int m = 0; m < 2; m++) a[m] = A[(lane + 32*m)*GSTR + k];
        #pragma unroll
        for (int i = 0; i < 8; i++) {
            float vv = Vs[(c0 + i)*128 + k];
            #pragma unroll
            for (int m = 0; m < 2; m++) acc[i][m] += vv * a[m];
        }
    }
    int wbase = h*128 + half*64 + lane;
    #pragma unroll
    for (int i = 0; i < 8; i++)
        #pragma unroll
        for (int m = 0; m < 2; m++)
            out[(c0 + i)*NPIX + wbase + 32*m] = acc[i][m];
}

// ---------------------------------------------------------------------------
extern "C" void kernel_launch(void* const* d_in, const int* in_sizes, int n_in,
                              void* d_out, int out_size)
{
    const float* x  = (const float*)d_in[0];
    const float* Wq = (const float*)d_in[1];
    const float* bq = (const float*)d_in[2];
    const float* Wk = (const float*)d_in[3];
    const float* bk = (const float*)d_in[4];
    const float* Wv = (const float*)d_in[5];
    const float* bv = (const float*)d_in[6];
    float* out = (float*)d_out;

    const int smem2 = (8192 + 8192 + 128*GSTR) * 4;   // 131584 B
    const int smem4 = (64*GSTR + 64*128) * 4;         //  65792 B
    cudaFuncSetAttribute(rowgram_kernel,  cudaFuncAttributeMaxDynamicSharedMemorySize, smem2);
    cudaFuncSetAttribute(attn_out_kernel, cudaFuncAttributeMaxDynamicSharedMemorySize, smem4);

    dim3 qkv_grid(32, 3);
    qkv_kernel<<<qkv_grid, 512>>>(x, Wq, bq, Wk, bk, Wv, bv);
    rowgram_kernel<<<128, 512, smem2>>>();
    hbox_kernel<<<4096, 256>>>();
    prefix_kernel<<<96, 256>>>();
    attn_out_kernel<<<256, 256, smem4>>>(out);
}

// round 5
// speedup vs baseline: 1.6758x; 1.0837x over previous
#include <cuda_runtime.h>

#define HH 128
#define WW 128
#define CC 64
#define NPIX (HH*WW)
#define GSTR 129

// scratch (allocation-free: __device__ globals)
__device__ float g_q[HH*CC*WW];   // [h][c][w]
__device__ float g_k[HH*CC*WW];   // [h][c][w]
__device__ float g_v[CC*HH*WW];   // [c][h][w]
__device__ float g_S[HH*WW*WW];   // [r][w][k]  (after prefix: PS over r)
__device__ float g_tmp[CC*HH*WW]; // [c][h][k]  (after prefix: prefix over h)

// ---------------------------------------------------------------------------
// Fused QKV: grid (32, 3); blockIdx.y selects which of q/k/v this block does.
// ---------------------------------------------------------------------------
__global__ __launch_bounds__(512) void qkv_kernel(const float* __restrict__ x,
                                                  const float* __restrict__ Wq,
                                                  const float* __restrict__ bq,
                                                  const float* __restrict__ Wk,
                                                  const float* __restrict__ bk,
                                                  const float* __restrict__ Wv,
                                                  const float* __restrict__ bv)
{
    __shared__ float Ws[64*64];
    __shared__ float bs[64];
    int dest = blockIdx.y;
    const float* Wm   = (dest == 0) ? Wq : (dest == 1) ? Wk : Wv;
    const float* bias = (dest == 0) ? bq : (dest == 1) ? bk : bv;
    int tid = threadIdx.x;
    for (int i = tid; i < 4096; i += 512) Ws[i] = Wm[i];
    if (tid < 64) bs[tid] = bias[tid];
    __syncthreads();

    int slot = tid & 127;
    int quarter = tid >> 7;
    int nbase = blockIdx.x * 512 + slot;

    float acc[16][4];
    #pragma unroll
    for (int i = 0; i < 16; i++)
        #pragma unroll
        for (int p = 0; p < 4; p++) acc[i][p] = 0.f;

    #pragma unroll 2
    for (int c = 0; c < 64; c++) {
        float xv[4];
        #pragma unroll
        for (int p = 0; p < 4; p++) xv[p] = x[c * NPIX + nbase + 128 * p];
        #pragma unroll
        for (int i = 0; i < 16; i++) {
            float wv = Ws[(quarter*16 + i)*64 + c];
            #pragma unroll
            for (int p = 0; p < 4; p++) acc[i][p] += wv * xv[p];
        }
    }

    float* out = (dest == 0) ? g_q : (dest == 1) ? g_k : g_v;
    #pragma unroll
    for (int i = 0; i < 16; i++) {
        int ch = quarter*16 + i;
        float b = bs[ch];
        #pragma unroll
        for (int p = 0; p < 4; p++) {
            int n = nbase + 128 * p;
            float val = acc[i][p] + b;
            if (dest < 2) {
                int h = n >> 7, w = n & 127;
                out[h*(CC*WW) + ch*WW + w] = val;
            } else {
                out[ch*NPIX + n] = val;
            }
        }
    }
}

// ---------------------------------------------------------------------------
// Per-row Gram G_r = Q_r^T K_r (64-deep), then diagonal 7-sum -> S_r.
// ---------------------------------------------------------------------------
__global__ __launch_bounds__(512) void rowgram_kernel()
{
    extern __shared__ float sm[];
    float* Qs = sm;            // 64 x 128
    float* Ks = sm + 8192;     // 64 x 128
    float* G  = sm + 16384;    // 128 x GSTR

    int r = blockIdx.x;
    int tid = threadIdx.x;
    const float* qrow = g_q + r * 8192;
    const float* krow = g_k + r * 8192;
    for (int i = tid; i < 8192; i += 512) { Qs[i] = qrow[i]; Ks[i] = krow[i]; }
    __syncthreads();

    int lane = tid & 31, warp = tid >> 5;    // 16 warps
    int b0 = warp * 8;
    float acc[4][8];
    #pragma unroll
    for (int m = 0; m < 4; m++)
        #pragma unroll
        for (int j = 0; j < 8; j++) acc[m][j] = 0.f;

    #pragma unroll 4
    for (int c = 0; c < 64; c++) {
        float qv[4];
        #pragma unroll
        for (int m = 0; m < 4; m++) qv[m] = Qs[c*128 + lane + 32*m];
        #pragma unroll
        for (int j = 0; j < 8; j++) {
            float kv = Ks[c*128 + b0 + j];
            #pragma unroll
            for (int m = 0; m < 4; m++) acc[m][j] += qv[m] * kv;
        }
    }
    #pragma unroll
    for (int m = 0; m < 4; m++)
        #pragma unroll
        for (int j = 0; j < 8; j++)
            G[(lane + 32*m)*GSTR + b0 + j] = acc[m][j];
    __syncthreads();

    // S_r[w,k] = sum_{j=0..6} G[w-3+j, k-3+j] (OOB terms are zero)
    float* Sout = g_S + r * 16384;
    for (int idx = tid; idx < 16384; idx += 512) {
        int w = idx >> 7, k = idx & 127;
        float s = 0.f;
        #pragma unroll
        for (int j = 0; j < 7; j++) {
            int a = w - 3 + j, b = k - 3 + j;
            if (a >= 0 && a < 128 && b >= 0 && b < 128)
                s += G[a*GSTR + b];
        }
        Sout[idx] = s;
    }
}

// ---------------------------------------------------------------------------
// Horizontal 7-sum of v (over k).
// ---------------------------------------------------------------------------
__global__ __launch_bounds__(256) void hbox_kernel()
{
    int idx = blockIdx.x * 256 + threadIdx.x;   // over [c][h][k]
    int k = idx & 127;
    float s = 0.f;
    #pragma unroll
    for (int j = 0; j < 7; j++) {
        int kk = k - 3 + j;
        if (kk >= 0 && kk < 128) s += g_v[idx + (kk - k)];
    }
    g_tmp[idx] = s;
}

// ---------------------------------------------------------------------------
// In-place prefix sums: g_S over r (16384 chains), g_tmp over h (8192 chains).
// MLP=8: load 8 rows as independent LDGs, then serial add+store.
// ---------------------------------------------------------------------------
__global__ __launch_bounds__(256) void prefix_kernel()
{
    int t = blockIdx.x * 256 + threadIdx.x;
    float vals[8];
    if (t < 16384) {
        float s = 0.f;
        float* p = g_S + t;
        for (int rb = 0; rb < 128; rb += 8) {
            #pragma unroll
            for (int i = 0; i < 8; i++) vals[i] = p[(rb + i) * 16384];
            #pragma unroll
            for (int i = 0; i < 8; i++) { s += vals[i]; p[(rb + i) * 16384] = s; }
        }
    } else {
        int u = t - 16384;
        int c = u >> 7, k = u & 127;
        float s = 0.f;
        float* p = g_tmp + c * NPIX + k;
        for (int hb = 0; hb < 128; hb += 8) {
            #pragma unroll
            for (int i = 0; i < 8; i++) vals[i] = p[(hb + i) * 128];
            #pragma unroll
            for (int i = 0; i < 8; i++) { s += vals[i]; p[(hb + i) * 128] = s; }
        }
    }
}

// ---------------------------------------------------------------------------
// Per (h, w-half): A = PS[r1]-PS[r0-1]; softmax_k; Vs = Ptmp diff;
// out = attn @ Vs^T. 256 blocks x 256 threads, ~66KB smem -> 3 blocks/SM.
// ---------------------------------------------------------------------------
__global__ __launch_bounds__(256) void attn_out_kernel(float* __restrict__ out)
{
    extern __shared__ float sm[];
    float* A  = sm;                 // [64 local w][k], stride GSTR
    float* Vs = sm + 64*GSTR;       // [c=64][k=128]

    int h    = blockIdx.x >> 1;
    int half = blockIdx.x & 1;
    int tid = threadIdx.x;
    int lane = tid & 31, warp = tid >> 5;    // 8 warps

    int r0 = (h - 3 < 0) ? 0 : h - 3;
    int r1 = (h + 3 > 127) ? 127 : h + 3;
    const float* PS1 = g_S + r1 * 16384 + half * 8192;
    const float* PS0 = (r0 > 0) ? (g_S + (r0 - 1) * 16384 + half * 8192) : nullptr;
    for (int idx = tid; idx < 8192; idx += 256) {
        float s = PS1[idx];
        if (PS0) s -= PS0[idx];
        int wl = idx >> 7, k = idx & 127;
        A[wl*GSTR + k] = s;
    }

    int top = (h + 3 > 127) ? 127 : h + 3;
    int bot = h - 4;
    for (int i = tid; i < 8192; i += 256) {
        int c = i >> 7, k = i & 127;
        float s = g_tmp[c*NPIX + top*128 + k];
        if (bot >= 0) s -= g_tmp[c*NPIX + bot*128 + k];
        Vs[c*128 + k] = s;
    }
    __syncthreads();

    // softmax over k: one warp per local-w row (8 warps cover 64 rows)
    for (int w = warp; w < 64; w += 8) {
        float v[4];
        #pragma unroll
        for (int m = 0; m < 4; m++) v[m] = A[w*GSTR + lane + 32*m];
        float mx = fmaxf(fmaxf(v[0], v[1]), fmaxf(v[2], v[3]));
        #pragma unroll
        for (int off = 16; off > 0; off >>= 1)
            mx = fmaxf(mx, __shfl_xor_sync(0xffffffffu, mx, off));
        float e[4], s = 0.f;
        #pragma unroll
        for (int m = 0; m < 4; m++) { e[m] = __expf(v[m] - mx); s += e[m]; }
        #pragma unroll
        for (int off = 16; off > 0; off >>= 1)
            s += __shfl_xor_sync(0xffffffffu, s, off);
        float inv = 1.f / s;
        #pragma unroll
        for (int m = 0; m < 4; m++) A[w*GSTR + lane + 32*m] = e[m] * inv;
    }
    __syncthreads();

    // out[c, h, half*64 + w] = sum_k A[w][k] * Vs[c][k]
    int c0 = warp * 8;
    float acc[8][2];
    #pragma unroll
    for (int i = 0; i < 8; i++)
        #pragma unroll
        for (int m = 0; m < 2; m++) acc[i][m] = 0.f;

    #pragma unroll 4
    for (int k = 0; k < 128; k++) {
        float a[2];
        #pragma unroll
        for (int m = 0; m < 2; m++) a[m] = A[(lane + 32*m)*GSTR + k];
        #pragma unroll
        for (int i = 0; i < 8; i++) {
            float vv = Vs[(c0 + i)*128 + k];
            #pragma unroll
            for (int m = 0; m < 2; m++) acc[i][m] += vv * a[m];
        }
    }
    int wbase = h*128 + half*64 + lane;
    #pragma unroll
    for (int i = 0; i < 8; i++)
        #pragma unroll
        for (int m = 0; m < 2; m++)
            out[(c0 + i)*NPIX + wbase + 32*m] = acc[i][m];
}

// ---------------------------------------------------------------------------
extern "C" void kernel_launch(void* const* d_in, const int* in_sizes, int n_in,
                              void* d_out, int out_size)
{
    const float* x  = (const float*)d_in[0];
    const float* Wq = (const float*)d_in[1];
    const float* bq = (const float*)d_in[2];
    const float* Wk = (const float*)d_in[3];
    const float* bk = (const float*)d_in[4];
    const float* Wv = (const float*)d_in[5];
    const float* bv = (const float*)d_in[6];
    float* out = (float*)d_out;

    const int smem2 = (8192 + 8192 + 128*GSTR) * 4;   // 131584 B
    const int smem4 = (64*GSTR + 64*128) * 4;         //  65792 B
    cudaFuncSetAttribute(rowgram_kernel,  cudaFuncAttributeMaxDynamicSharedMemorySize, smem2);
    cudaFuncSetAttribute(attn_out_kernel, cudaFuncAttributeMaxDynamicSharedMemorySize, smem4);

    dim3 qkv_grid(32, 3);
    qkv_kernel<<<qkv_grid, 512>>>(x, Wq, bq, Wk, bk, Wv, bv);
    rowgram_kernel<<<128, 512, smem2>>>();
    hbox_kernel<<<4096, 256>>>();
    prefix_kernel<<<96, 256>>>();
    attn_out_kernel<<<256, 256, smem4>>>(out);
}